// round 1
// baseline (speedup 1.0000x reference)
#include <cuda_runtime.h>

#define NG      512
#define NODES   200
#define EDGES   6400
#define HID     128
#define TPB     256

// MLP intermediate buffers (no cudaMalloc allowed)
__device__ float g_hg[NG * HID];
__device__ float g_x1[NG * 512];
__device__ float g_x2[NG * 1024];
__device__ float g_x3[NG * 1024];
__device__ float g_x4[NG * 512];

// ---------------------------------------------------------------------------
// Per-graph GNN kernel: degrees -> CSR -> layer1 (scalar) -> GEMM(hv@W2) ->
// layer2 scatter -> mean pool. One CTA per graph, everything in SMEM.
// SMEM layout (floats):
//   bufA[200*128]  : hv, later h2
//   bufB[200*128]  : t = (hv@W2)*inv_out, later pool partials
//   s_s/s_a/s_ii/s_io[200]
//   Wt[16*128]     : staged W2 k-tile
//   ints: cnt[204], cur[204], odeg[204]
//   csr : uint8[6400] (src local ids, sorted by dst)
// Total = 225,040 bytes (< 227 KB opt-in limit)
// ---------------------------------------------------------------------------
__global__ void __launch_bounds__(TPB, 1) gnn_kernel(
    const int*   __restrict__ src, const int*   __restrict__ dst,
    const float* __restrict__ W1,  const float* __restrict__ b1,
    const float* __restrict__ W2,  const float* __restrict__ b2,
    float* __restrict__ hg)
{
    extern __shared__ float sf[];
    float* bufA = sf;                       // 25600 floats
    float* bufB = sf + NODES * HID;         // 25600 floats
    float* s_s  = sf + 2 * NODES * HID;     // 200
    float* s_a  = s_s + NODES;              // 200
    float* s_ii = s_a + NODES;              // 200
    float* s_io = s_ii + NODES;             // 200
    float* Wt   = s_io + NODES;             // 2048 floats (16x128)
    int*   cnt  = (int*)(Wt + 2048);        // 204
    int*   cur  = cnt + 204;                // 204
    int*   odeg = cur + 204;                // 204
    unsigned char* csr = (unsigned char*)(odeg + 204); // 6400 bytes

    const int tid   = threadIdx.x;
    const int g     = blockIdx.x;
    const int ebase = g * EDGES;
    const int nbase = g * NODES;

    // --- degrees ---
    for (int i = tid; i < NODES; i += TPB) { cnt[i] = 0; odeg[i] = 0; }
    __syncthreads();
    for (int e = tid; e < EDGES; e += TPB) {
        int sl = src[ebase + e] - nbase;
        int dl = dst[ebase + e] - nbase;
        atomicAdd(&cnt[dl], 1);
        atomicAdd(&odeg[sl], 1);
    }
    __syncthreads();
    for (int i = tid; i < NODES; i += TPB) {
        float idg = (float)cnt[i];
        float odg = (float)odeg[i];
        float ii = rsqrtf(fmaxf(idg, 1.0f));
        float io = rsqrtf(fmaxf(odg, 1.0f));
        s_ii[i] = ii;
        s_io[i] = io;
        s_s[i]  = idg * io;      // s = in_deg * inv_out (layer-1 per-src scalar)
    }
    __syncthreads();
    // --- exclusive scan of in-degree counts (serial, tiny) ---
    if (tid == 0) {
        int run = 0;
        for (int i = 0; i < NODES; i++) { int c = cnt[i]; cnt[i] = run; cur[i] = run; run += c; }
        cnt[NODES] = run;
    }
    __syncthreads();
    // --- CSR fill: src local ids grouped by dst ---
    for (int e = tid; e < EDGES; e += TPB) {
        int sl = src[ebase + e] - nbase;
        int dl = dst[ebase + e] - nbase;
        int p  = atomicAdd(&cur[dl], 1);
        csr[p] = (unsigned char)sl;
    }
    __syncthreads();
    // --- layer-1 aggregation (scalar per dst) ---
    for (int d = tid; d < NODES; d += TPB) {
        float sum = 0.0f;
        int p0 = cnt[d], p1 = cnt[d + 1];
        for (int p = p0; p < p1; p++) sum += s_s[csr[p]];
        s_a[d] = sum * s_ii[d];
    }
    __syncthreads();
    // --- hv[i][k] = relu(a[i]*W1[k] + b1[k]) into bufA ---
    {
        const float4* W1v = (const float4*)W1;
        const float4* b1v = (const float4*)b1;
        for (int idx = tid; idx < NODES * 32; idx += TPB) {
            int i = idx >> 5, k4 = idx & 31;
            float av = s_a[i];
            float4 w = W1v[k4], bb = b1v[k4];
            float4 h;
            h.x = fmaxf(fmaf(av, w.x, bb.x), 0.0f);
            h.y = fmaxf(fmaf(av, w.y, bb.y), 0.0f);
            h.z = fmaxf(fmaf(av, w.z, bb.z), 0.0f);
            h.w = fmaxf(fmaf(av, w.w, bb.w), 0.0f);
            ((float4*)bufA)[idx] = h;
        }
    }
    __syncthreads();
    // --- GEMM: bufB[i][j] = inv_out[i] * sum_k bufA[i][k] * W2[k][j] ---
    const int tx = tid & 31;   // 32 float4 column groups -> 128 cols
    const int ty = tid >> 5;   // 8 warps
    const float4* W2v = (const float4*)W2;
    float4* Wt4 = (float4*)Wt;
    for (int rb = 0; rb < 7; ++rb) {
        int r[4], rc[4];
        #pragma unroll
        for (int m = 0; m < 4; m++) {
            r[m]  = rb * 32 + m * 8 + ty;
            rc[m] = (r[m] < NODES) ? r[m] : 0;
        }
        float4 acc[4] = {{0,0,0,0},{0,0,0,0},{0,0,0,0},{0,0,0,0}};
        for (int kt = 0; kt < 8; ++kt) {
            // stage 16x128 W2 tile into SMEM
            #pragma unroll
            for (int t = 0; t < 2; t++) {
                int i4 = tid + t * TPB;
                Wt4[i4] = W2v[kt * 512 + i4];
            }
            __syncthreads();
            #pragma unroll
            for (int kk = 0; kk < 16; kk += 4) {
                float4 a4[4];
                #pragma unroll
                for (int m = 0; m < 4; m++)
                    a4[m] = *(const float4*)(bufA + rc[m] * HID + kt * 16 + kk);
                #pragma unroll
                for (int q = 0; q < 4; q++) {
                    float4 w = Wt4[(kk + q) * 32 + tx];
                    #pragma unroll
                    for (int m = 0; m < 4; m++) {
                        float av = ((const float*)&a4[m])[q];
                        acc[m].x = fmaf(av, w.x, acc[m].x);
                        acc[m].y = fmaf(av, w.y, acc[m].y);
                        acc[m].z = fmaf(av, w.z, acc[m].z);
                        acc[m].w = fmaf(av, w.w, acc[m].w);
                    }
                }
            }
            __syncthreads();
        }
        #pragma unroll
        for (int m = 0; m < 4; m++) {
            if (r[m] < NODES) {
                float io = s_io[r[m]];
                float4 o = acc[m];
                o.x *= io; o.y *= io; o.z *= io; o.w *= io;
                ((float4*)bufB)[r[m] * 32 + tx] = o;
            }
        }
    }
    __syncthreads();
    // --- layer-2 aggregation: h2[d] = relu((sum_{e->d} t[src]) * inv_in[d] + b2)
    {
        float4 bb2 = ((const float4*)b2)[tx];
        for (int d = ty; d < NODES; d += 8) {   // warp per dst
            int p0 = cnt[d], p1 = cnt[d + 1];
            float4 acc = {0, 0, 0, 0};
            for (int p = p0; p < p1; ++p) {
                int sv = csr[p];
                float4 v = ((const float4*)bufB)[sv * 32 + tx];
                acc.x += v.x; acc.y += v.y; acc.z += v.z; acc.w += v.w;
            }
            float ii = s_ii[d];
            float4 h;
            h.x = fmaxf(fmaf(acc.x, ii, bb2.x), 0.0f);
            h.y = fmaxf(fmaf(acc.y, ii, bb2.y), 0.0f);
            h.z = fmaxf(fmaf(acc.z, ii, bb2.z), 0.0f);
            h.w = fmaxf(fmaf(acc.w, ii, bb2.w), 0.0f);
            ((float4*)bufA)[d * 32 + tx] = h;
        }
    }
    __syncthreads();
    // --- mean pool over 200 nodes ---
    {
        int f4 = tid & 31;
        int chunk = tid >> 5;
        float4 acc = {0, 0, 0, 0};
        for (int rr = chunk * 25; rr < chunk * 25 + 25; ++rr) {
            float4 v = ((const float4*)bufA)[rr * 32 + f4];
            acc.x += v.x; acc.y += v.y; acc.z += v.z; acc.w += v.w;
        }
        ((float4*)bufB)[chunk * 32 + f4] = acc;
    }
    __syncthreads();
    if (tid < 32) {
        float4 t = {0, 0, 0, 0};
        for (int c = 0; c < 8; c++) {
            float4 v = ((const float4*)bufB)[c * 32 + tid];
            t.x += v.x; t.y += v.y; t.z += v.z; t.w += v.w;
        }
        const float inv = 1.0f / 200.0f;
        t.x *= inv; t.y *= inv; t.z *= inv; t.w *= inv;
        ((float4*)(hg + g * HID))[tid] = t;
    }
}

// ---------------------------------------------------------------------------
// Tiled fp32 GEMM: C = relu(A @ W + bias). 64x64 tile per CTA, 256 threads,
// each thread 4x4 outputs. Requires M%64==0, Nc%64==0, K%16==0.
// ---------------------------------------------------------------------------
__global__ void __launch_bounds__(256) gemm_bias_relu(
    const float* __restrict__ A, const float* __restrict__ W,
    const float* __restrict__ bias, float* __restrict__ C,
    int M, int K, int Nc)
{
    __shared__ float As[64 * 16];
    __shared__ float Ws[16 * 64];
    const int tid = threadIdx.x;
    const int tx = tid & 15, ty = tid >> 4;
    const int row0 = blockIdx.y * 64, col0 = blockIdx.x * 64;

    float4 acc[4] = {{0,0,0,0},{0,0,0,0},{0,0,0,0},{0,0,0,0}};

    for (int kt = 0; kt < K; kt += 16) {
        { // A tile: 64x16
            int r = tid >> 2, kq = tid & 3;
            ((float4*)As)[tid] = *(const float4*)(A + (size_t)(row0 + r) * K + kt + kq * 4);
        }
        { // W tile: 16x64
            int kk = tid >> 4, cq = tid & 15;
            ((float4*)Ws)[tid] = *(const float4*)(W + (size_t)(kt + kk) * Nc + col0 + cq * 4);
        }
        __syncthreads();
        #pragma unroll
        for (int kk = 0; kk < 16; kk++) {
            float4 w = ((float4*)Ws)[kk * 16 + tx];
            #pragma unroll
            for (int i = 0; i < 4; i++) {
                float a = As[(ty * 4 + i) * 16 + kk];
                acc[i].x = fmaf(a, w.x, acc[i].x);
                acc[i].y = fmaf(a, w.y, acc[i].y);
                acc[i].z = fmaf(a, w.z, acc[i].z);
                acc[i].w = fmaf(a, w.w, acc[i].w);
            }
        }
        __syncthreads();
    }
    float4 bv = *(const float4*)(bias + col0 + tx * 4);
    #pragma unroll
    for (int i = 0; i < 4; i++) {
        float4 o = acc[i];
        o.x = fmaxf(o.x + bv.x, 0.0f);
        o.y = fmaxf(o.y + bv.y, 0.0f);
        o.z = fmaxf(o.z + bv.z, 0.0f);
        o.w = fmaxf(o.w + bv.w, 0.0f);
        *(float4*)(C + (size_t)(row0 + ty * 4 + i) * Nc + col0 + tx * 4) = o;
    }
}

// ---------------------------------------------------------------------------
// Final layer: out = softmax(A(512x512) @ We(512x10) + be). Warp per row.
// ---------------------------------------------------------------------------
__global__ void __launch_bounds__(256) head_softmax(
    const float* __restrict__ A, const float* __restrict__ We,
    const float* __restrict__ be, float* __restrict__ out)
{
    __shared__ float Ws[512 * 10];
    const int tid = threadIdx.x;
    for (int i = tid; i < 512 * 10; i += 256) Ws[i] = We[i];
    __syncthreads();
    const int lane = tid & 31, w = tid >> 5;
    const int row = blockIdx.x * 8 + w;

    float acc[10];
    #pragma unroll
    for (int c = 0; c < 10; c++) acc[c] = 0.0f;
    for (int k = lane; k < 512; k += 32) {
        float a = A[row * 512 + k];
        #pragma unroll
        for (int c = 0; c < 10; c++) acc[c] = fmaf(a, Ws[k * 10 + c], acc[c]);
    }
    #pragma unroll
    for (int c = 0; c < 10; c++) {
        #pragma unroll
        for (int o = 16; o > 0; o >>= 1)
            acc[c] += __shfl_xor_sync(0xffffffffu, acc[c], o);
    }
    if (lane == 0) {
        float v[10], mx = -1e30f;
        #pragma unroll
        for (int c = 0; c < 10; c++) { v[c] = acc[c] + be[c]; mx = fmaxf(mx, v[c]); }
        float s = 0.0f;
        #pragma unroll
        for (int c = 0; c < 10; c++) { v[c] = __expf(v[c] - mx); s += v[c]; }
        float inv = 1.0f / s;
        #pragma unroll
        for (int c = 0; c < 10; c++) out[row * 10 + c] = v[c] * inv;
    }
}

// ---------------------------------------------------------------------------
extern "C" void kernel_launch(void* const* d_in, const int* in_sizes, int n_in,
                              void* d_out, int out_size)
{
    const int*   src = (const int*)  d_in[0];
    const int*   dst = (const int*)  d_in[1];
    const float* W1  = (const float*)d_in[2];
    const float* b1  = (const float*)d_in[3];
    const float* W2  = (const float*)d_in[4];
    const float* b2  = (const float*)d_in[5];
    const float* Wa  = (const float*)d_in[6];
    const float* ba  = (const float*)d_in[7];
    const float* Wb  = (const float*)d_in[8];
    const float* bb  = (const float*)d_in[9];
    const float* Wc  = (const float*)d_in[10];
    const float* bc  = (const float*)d_in[11];
    const float* Wd  = (const float*)d_in[12];
    const float* bd  = (const float*)d_in[13];
    const float* We  = (const float*)d_in[14];
    const float* be  = (const float*)d_in[15];
    float* out = (float*)d_out;

    float *hg, *x1, *x2, *x3, *x4;
    cudaGetSymbolAddress((void**)&hg, g_hg);
    cudaGetSymbolAddress((void**)&x1, g_x1);
    cudaGetSymbolAddress((void**)&x2, g_x2);
    cudaGetSymbolAddress((void**)&x3, g_x3);
    cudaGetSymbolAddress((void**)&x4, g_x4);

    const int SMEM = 225040;  // see layout comment in gnn_kernel
    cudaFuncSetAttribute(gnn_kernel, cudaFuncAttributeMaxDynamicSharedMemorySize, SMEM);

    gnn_kernel<<<NG, TPB, SMEM>>>(src, dst, W1, b1, W2, b2, hg);

    gemm_bias_relu<<<dim3(512 / 64,  512 / 64), 256>>>(hg, Wa, ba, x1, 512, 128,  512);
    gemm_bias_relu<<<dim3(1024 / 64, 512 / 64), 256>>>(x1, Wb, bb, x2, 512, 512,  1024);
    gemm_bias_relu<<<dim3(1024 / 64, 512 / 64), 256>>>(x2, Wc, bc, x3, 512, 1024, 1024);
    gemm_bias_relu<<<dim3(512 / 64,  512 / 64), 256>>>(x3, Wd, bd, x4, 512, 1024, 512);

    head_softmax<<<64, 256>>>(x4, We, be, out);
}